// round 14
// baseline (speedup 1.0000x reference)
#include <cuda_runtime.h>
#include <cuda_bf16.h>
#include <cstdint>

#define NNODES 50000
#define NEDGES 1600000

// ---------------- scratch (static device globals; no allocation) -------------
__device__ float g_T1[(size_t)NNODES * 512];
__device__ float g_T2[(size_t)NNODES * 512];
__device__ float g_h1[(size_t)NNODES * 250];
__device__ float g_h2[(size_t)NNODES * 500];
__device__ int   g_deg[NNODES];
__device__ float g_dinv[NNODES];
__device__ float g_diag[NNODES];
__device__ int   g_off[NNODES + 1];
__device__ int   g_cursor[NNODES];
__device__ int   g_ccol[NEDGES];
__device__ float g_cw[NEDGES];
__device__ int   g_row[NEDGES];
__device__ int   g_col[NEDGES];
__device__ int   g_is64;

// ---------------- preprocessing ---------------------------------------------
__global__ void k_zero(int* __restrict__ p, int n) {
    int i = blockIdx.x * blockDim.x + threadIdx.x;
    if (i < n) p[i] = 0;
}

// Detect whether edge_index buffer is int64 or int32.
// Reads only the first 64 int64 slots (512 bytes) — in-bounds for both layouts.
// If the data is int32, each int64 read fuses two random indices (hi word
// almost surely nonzero -> value >= NNODES), so "all 64 in range" => int64.
__global__ void k_detect(const long long* __restrict__ ei) {
    if (threadIdx.x == 0 && blockIdx.x == 0) {
        int ok = 1;
        for (int i = 0; i < 64; i++) {
            long long v = ei[i];
            if (v < 0 || v >= NNODES) { ok = 0; break; }
        }
        g_is64 = ok;
    }
}

__global__ void k_deg(const void* __restrict__ eiv, int* __restrict__ row,
                      int* __restrict__ col, int* __restrict__ deg) {
    int e = blockIdx.x * blockDim.x + threadIdx.x;
    if (e < NEDGES) {
        int c, r;
        if (g_is64) {
            const long long* ei = (const long long*)eiv;
            c = (int)ei[e];            // edge_index[0] = src (col)
            r = (int)ei[NEDGES + e];   // edge_index[1] = dst (row)
        } else {
            const int* ei = (const int*)eiv;
            c = ei[e];
            r = ei[NEDGES + e];
        }
        // bounds guard: wrong-dtype fallback degrades to wrong answer, not crash
        if ((unsigned)c >= NNODES) c = 0;
        if ((unsigned)r >= NNODES) r = 0;
        row[e] = r;
        col[e] = c;
        atomicAdd(&deg[r], 1);
    }
}

__global__ void k_dinv(const int* __restrict__ deg, float* __restrict__ dinv,
                       float* __restrict__ diag) {
    int v = blockIdx.x * blockDim.x + threadIdx.x;
    if (v < NNODES) {
        int d = deg[v];
        dinv[v] = (d > 0) ? rsqrtf((float)d) : 0.0f;
        diag[v] = (d > 0) ? 0.0f : -1.0f;
    }
}

// single-block chunked Hillis-Steele exclusive scan -> CSR offsets + cursors
__global__ void k_scan(const int* __restrict__ deg, int* __restrict__ off,
                       int* __restrict__ cursor) {
    __shared__ int sh[1024];
    __shared__ int carry;
    int t = threadIdx.x;
    if (t == 0) carry = 0;
    __syncthreads();
    for (int base = 0; base < NNODES; base += 1024) {
        int i = base + t;
        int v = (i < NNODES) ? deg[i] : 0;
        sh[t] = v;
        __syncthreads();
        for (int ofs = 1; ofs < 1024; ofs <<= 1) {
            int x = (t >= ofs) ? sh[t - ofs] : 0;
            __syncthreads();
            sh[t] += x;
            __syncthreads();
        }
        int excl = carry + sh[t] - v;
        if (i < NNODES) { off[i] = excl; cursor[i] = excl; }
        __syncthreads();
        if (t == 1023) carry += sh[1023];
        __syncthreads();
    }
    if (t == 0) off[NNODES] = carry;
}

__global__ void k_csr(const int* __restrict__ row, const int* __restrict__ col,
                      const float* __restrict__ dinv, int* __restrict__ cursor,
                      int* __restrict__ ccol, float* __restrict__ cw) {
    int e = blockIdx.x * blockDim.x + threadIdx.x;
    if (e < NEDGES) {
        int r = row[e], c = col[e];
        int pos = atomicAdd(&cursor[r], 1);
        ccol[pos] = c;
        cw[pos] = -dinv[r] * dinv[c];
    }
}

// ---------------- Lhat aggregation (atomic-free, CSR gather) ------------------
// mode 0: out = agg(h) + diag*h                 (T1 = Lhat(h))
// mode 1: out = 2*(agg(h) + diag*h) - t0        (T2 = 2*Lhat(T1) - T0)
__global__ void k_lhat(const float* __restrict__ h, const float* __restrict__ t0,
                       const int* __restrict__ off, const int* __restrict__ ccol,
                       const float* __restrict__ cw, const float* __restrict__ diag,
                       float* __restrict__ out, int F, int mode) {
    int v = blockIdx.x;
    int f = blockIdx.y * blockDim.x + threadIdx.x;
    if (f >= F) return;
    int e0 = off[v], e1 = off[v + 1];
    float acc = 0.0f;
    int e = e0;
    for (; e + 4 <= e1; e += 4) {
        int c0 = ccol[e + 0], c1 = ccol[e + 1], c2 = ccol[e + 2], c3 = ccol[e + 3];
        float w0 = cw[e + 0], w1 = cw[e + 1], w2 = cw[e + 2], w3 = cw[e + 3];
        float h0 = h[(size_t)c0 * F + f];
        float h1 = h[(size_t)c1 * F + f];
        float h2 = h[(size_t)c2 * F + f];
        float h3 = h[(size_t)c3 * F + f];
        acc += w0 * h0 + w1 * h1 + w2 * h2 + w3 * h3;
    }
    for (; e < e1; ++e) {
        int c = ccol[e];
        acc += cw[e] * h[(size_t)c * F + f];
    }
    acc += diag[v] * h[(size_t)v * F + f];
    if (mode) acc = 2.0f * acc - t0[(size_t)v * F + f];
    out[(size_t)v * F + f] = acc;
}

// ---------------- fused 3-term GEMM + bias + relu ----------------------------
// out[M,N] = relu(T0@W[0] + T1@W[1] + T2@W[2] + bias),  W is [3,K,N] row-major
#define BM 128
#define BN 128
#define BKK 8
#define TM 8
#define TN 8

__global__ __launch_bounds__(256) void k_gemm3(
    const float* __restrict__ A0, const float* __restrict__ A1,
    const float* __restrict__ A2, const float* __restrict__ W,
    const float* __restrict__ bias, float* __restrict__ out,
    int M, int N, int K) {
    __shared__ float As[BKK][BM];
    __shared__ float Bs[BKK][BN];
    int bm = blockIdx.y * BM, bn = blockIdx.x * BN;
    int t = threadIdx.x;
    int tx = t & 15, ty = t >> 4;      // 16x16 thread grid
    float acc[TM][TN];
#pragma unroll
    for (int i = 0; i < TM; i++)
#pragma unroll
        for (int j = 0; j < TN; j++) acc[i][j] = 0.0f;

    const float* Aptr[3] = {A0, A1, A2};
    for (int kk = 0; kk < 3; ++kk) {
        const float* A = Aptr[kk];
        const float* B = W + (size_t)kk * K * N;
        for (int k0 = 0; k0 < K; k0 += BKK) {
            // load A tile 128x8 (store transposed)
#pragma unroll
            for (int i = 0; i < 4; i++) {
                int idx = i * 256 + t;
                int m = idx >> 3, kc = idx & 7;
                int gm = bm + m, gk = k0 + kc;
                As[kc][m] = (gm < M && gk < K) ? A[(size_t)gm * K + gk] : 0.0f;
            }
            // load B tile 8x128 (coalesced along N)
#pragma unroll
            for (int i = 0; i < 4; i++) {
                int idx = i * 256 + t;
                int kc = idx >> 7, n = idx & 127;
                int gk = k0 + kc, gn = bn + n;
                Bs[kc][n] = (gk < K && gn < N) ? B[(size_t)gk * N + gn] : 0.0f;
            }
            __syncthreads();
#pragma unroll
            for (int kb = 0; kb < BKK; kb++) {
                float a[TM], b[TN];
                float4 a0 = *reinterpret_cast<const float4*>(&As[kb][ty * TM]);
                float4 a1 = *reinterpret_cast<const float4*>(&As[kb][ty * TM + 4]);
                float4 b0 = *reinterpret_cast<const float4*>(&Bs[kb][tx * TN]);
                float4 b1 = *reinterpret_cast<const float4*>(&Bs[kb][tx * TN + 4]);
                a[0] = a0.x; a[1] = a0.y; a[2] = a0.z; a[3] = a0.w;
                a[4] = a1.x; a[5] = a1.y; a[6] = a1.z; a[7] = a1.w;
                b[0] = b0.x; b[1] = b0.y; b[2] = b0.z; b[3] = b0.w;
                b[4] = b1.x; b[5] = b1.y; b[6] = b1.z; b[7] = b1.w;
#pragma unroll
                for (int i = 0; i < TM; i++)
#pragma unroll
                    for (int j = 0; j < TN; j++) acc[i][j] += a[i] * b[j];
            }
            __syncthreads();
        }
    }
#pragma unroll
    for (int i = 0; i < TM; i++) {
        int gm = bm + ty * TM + i;
        if (gm >= M) continue;
#pragma unroll
        for (int j = 0; j < TN; j++) {
            int gn = bn + tx * TN + j;
            if (gn < N) {
                float v = acc[i][j] + bias[gn];
                out[(size_t)gm * N + gn] = fmaxf(v, 0.0f);
            }
        }
    }
}

// ---------------- launch ------------------------------------------------------
static inline int cdiv(int a, int b) { return (a + b - 1) / b; }

extern "C" void kernel_launch(void* const* d_in, const int* in_sizes, int n_in,
                              void* d_out, int out_size) {
    const float* x  = (const float*)d_in[0];
    const void*  ei = d_in[1];               // int32 or int64 — detected on device
    const float* w1 = (const float*)d_in[2];
    const float* b1 = (const float*)d_in[3];
    const float* w2 = (const float*)d_in[4];
    const float* b2 = (const float*)d_in[5];
    const float* w3 = (const float*)d_in[6];
    const float* b3 = (const float*)d_in[7];
    float* out = (float*)d_out;

    float *T1, *T2, *h1, *h2, *dinv, *diag, *cw;
    int *row, *col, *deg, *off, *cursor, *ccol;
    cudaGetSymbolAddress((void**)&T1, g_T1);
    cudaGetSymbolAddress((void**)&T2, g_T2);
    cudaGetSymbolAddress((void**)&h1, g_h1);
    cudaGetSymbolAddress((void**)&h2, g_h2);
    cudaGetSymbolAddress((void**)&row, g_row);
    cudaGetSymbolAddress((void**)&col, g_col);
    cudaGetSymbolAddress((void**)&deg, g_deg);
    cudaGetSymbolAddress((void**)&dinv, g_dinv);
    cudaGetSymbolAddress((void**)&diag, g_diag);
    cudaGetSymbolAddress((void**)&off, g_off);
    cudaGetSymbolAddress((void**)&cursor, g_cursor);
    cudaGetSymbolAddress((void**)&ccol, g_ccol);
    cudaGetSymbolAddress((void**)&cw, g_cw);

    const int M = NNODES;

    // ---- preprocessing (runs every replay; kernels only) ----
    k_zero<<<cdiv(NNODES, 256), 256>>>(deg, NNODES);
    k_detect<<<1, 32>>>((const long long*)ei);
    k_deg<<<cdiv(NEDGES, 256), 256>>>(ei, row, col, deg);
    k_dinv<<<cdiv(NNODES, 256), 256>>>(deg, dinv, diag);
    k_scan<<<1, 1024>>>(deg, off, cursor);
    k_csr<<<cdiv(NEDGES, 256), 256>>>(row, col, dinv, cursor, ccol, cw);

    // ---- layer 1: F=512 -> 250 ----
    {
        int F = 512, N = 250, K = 512;
        dim3 lg(M, cdiv(F, 128));
        k_lhat<<<lg, 128>>>(x, nullptr, off, ccol, cw, diag, T1, F, 0);
        k_lhat<<<lg, 128>>>(T1, x, off, ccol, cw, diag, T2, F, 1);
        dim3 gg(cdiv(N, BN), cdiv(M, BM));
        k_gemm3<<<gg, 256>>>(x, T1, T2, w1, b1, h1, M, N, K);
    }
    // ---- layer 2: F=250 -> 500 ----
    {
        int F = 250, N = 500, K = 250;
        dim3 lg(M, cdiv(F, 128));
        k_lhat<<<lg, 128>>>(h1, nullptr, off, ccol, cw, diag, T1, F, 0);
        k_lhat<<<lg, 128>>>(T1, h1, off, ccol, cw, diag, T2, F, 1);
        dim3 gg(cdiv(N, BN), cdiv(M, BM));
        k_gemm3<<<gg, 256>>>(h1, T1, T2, w2, b2, h2, M, N, K);
    }
    // ---- layer 3: F=500 -> 1000 ----
    {
        int F = 500, N = 1000, K = 500;
        dim3 lg(M, cdiv(F, 128));
        k_lhat<<<lg, 128>>>(h2, nullptr, off, ccol, cw, diag, T1, F, 0);
        k_lhat<<<lg, 128>>>(T1, h2, off, ccol, cw, diag, T2, F, 1);
        dim3 gg(cdiv(N, BN), cdiv(M, BM));
        k_gemm3<<<gg, 256>>>(h2, T1, T2, w3, b3, out, M, N, K);
    }
}